// round 16
// baseline (speedup 1.0000x reference)
#include <cuda_runtime.h>
#include <cuda_fp16.h>
#include <math.h>
#include <stdint.h>

// ---------------- problem constants ----------------
#define NROWS 8192
#define IN_F  512
#define RFF   2048
#define OUT_F 1000
#define OUT_P 1024
#define KBIG  (3*IN_F)                 // 1536: [Dhi|Dlo|Dhi] x [Whi|Whi|Wlo] (fp16)
#define INV_RFF_SCALAR (1.0f/32.0f)
#define MFF   25.0f

// ---------------- fp16 tiling ----------------
#define BM 128
#define BN 128
#define BKB 64
#define LDSH 72                        // halves per smem row (144 B)
#define AB_BYTES (128*LDSH*2)          // 18432
#define STAGE_BYTES_B (2*AB_BYTES)     // 36864
#define NSTAGE 3
#define NTH 256                        // 8 warps, 2x4 grid, 64x32 warp tiles
#define GRID_P 296

// tile queue: prep [0,256), G1 [256,1280), G2 [1280,2304), G3 [2304,2816)
#define TP_D   32
#define TP_COV 160
#define TP_LW  224
#define TP_G1  256
#define TP_G2  1280
#define TP_G3  2304
#define T_END  2816

// sync layout
#define S_CTR 0
#define S_W   1
#define S_D   2     // 64 entries
#define S_COV 66
#define S_LW  67
#define S_G1  68    // 64 entries
#define S_G2  132   // 64 entries
#define S_TOT 196

// ---------------- device scratch ----------------
__device__ __half g_Phih [NROWS*RFF];
__device__ __half g_covh [RFF*RFF];
__device__ __half g_covh2[RFF*RFF];
__device__ __half g_lwh  [OUT_P*RFF];
__device__ __half g_Abh[NROWS*KBIG];
__device__ __half g_Bbh[RFF*KBIG];
__device__ float  g_diag_part[16*NROWS];
__device__ int    g_sync[S_TOT];

// ---------------- helpers ----------------
__device__ __forceinline__ uint32_t smem_u32(const void* p) {
    uint32_t r;
    asm("{ .reg .u64 t; cvta.to.shared.u64 t, %1; cvt.u32.u64 %0, t; }" : "=r"(r) : "l"(p));
    return r;
}
__device__ __forceinline__ void cp16(uint32_t d, const void* s) {
    asm volatile("cp.async.cg.shared.global [%0], [%1], 16;" :: "r"(d), "l"(s));
}
__device__ __forceinline__ void cp_commit() { asm volatile("cp.async.commit_group;"); }
template <int N> __device__ __forceinline__ void cp_wait() {
    asm volatile("cp.async.wait_group %0;" :: "n"(N));
}
__device__ __forceinline__ void ldsm_x4(uint32_t* r, uint32_t a) {
    asm volatile("ldmatrix.sync.aligned.m8n8.x4.shared.b16 {%0,%1,%2,%3}, [%4];"
        : "=r"(r[0]), "=r"(r[1]), "=r"(r[2]), "=r"(r[3]) : "r"(a));
}
__device__ __forceinline__ void mma_f16(float* c, const uint32_t* a, const uint32_t* b) {
    asm volatile(
        "mma.sync.aligned.m16n8k16.row.col.f32.f16.f16.f32 "
        "{%0,%1,%2,%3}, {%4,%5,%6,%7}, {%8,%9}, {%0,%1,%2,%3};"
        : "+f"(c[0]), "+f"(c[1]), "+f"(c[2]), "+f"(c[3])
        : "r"(a[0]), "r"(a[1]), "r"(a[2]), "r"(a[3]), "r"(b[0]), "r"(b[1]));
}

// ---------------- prep tile workers (noinline: keep mainloop reg budget) ----------------
__device__ __noinline__ void prep_w_tile(const float* __restrict__ W,
                                         __half* __restrict__ Bbh, float* tb,
                                         int w, int tid)
{
    const int tx = tid & 31, ty0 = tid >> 5;
    for (int b = w * 32; b < w * 32 + 32; b++) {
        const int nb = (b & 63) * 32, kb = (b >> 6) * 32;
        __syncthreads();
        #pragma unroll
        for (int i = 0; i < 32; i += 8)
            tb[(ty0 + i) * 33 + tx] = W[(size_t)(kb + ty0 + i) * RFF + nb + tx];
        __syncthreads();
        #pragma unroll
        for (int i = 0; i < 32; i += 8) {
            const int ty = ty0 + i;
            const int n = nb + ty, k = kb + tx;
            float x = tb[tx * 33 + ty];
            __half hi = __float2half(x);
            __half lo = __float2half(x - __half2float(hi));
            __half* p = Bbh + (size_t)n * KBIG;
            p[k] = hi; p[IN_F + k] = hi; p[2 * IN_F + k] = lo;
        }
    }
}

__device__ __noinline__ void prep_d_tile(const float* __restrict__ D,
                                         __half* __restrict__ Abh, int d, int tid)
{
    const int base = d * 32768;
    for (int j = 0; j < 128; j++) {
        const int idx = base + j * 256 + tid;
        const int r = idx >> 9, k = idx & (IN_F - 1);
        float x = D[idx];
        __half hi = __float2half(x);
        __half lo = __float2half(x - __half2float(hi));
        __half* p = Abh + (size_t)r * KBIG;
        p[k] = hi; p[IN_F + k] = lo; p[2 * IN_F + k] = hi;
    }
}

__device__ __noinline__ void prep_cov_tile(const float* __restrict__ cov,
                                           __half* __restrict__ covh,
                                           __half* __restrict__ covh2, int c, int tid)
{
    const int base = c * 65536;
    for (int j = 0; j < 64; j++) {
        const int idx = base + (j * 256 + tid) * 4;
        float4 v = *(const float4*)(cov + idx);
        __half2 a, b, a2, b2;
        a.x  = __float2half(v.x);        a.y  = __float2half(v.y);
        b.x  = __float2half(v.z);        b.y  = __float2half(v.w);
        a2.x = __float2half(2.0f * v.x); a2.y = __float2half(2.0f * v.y);
        b2.x = __float2half(2.0f * v.z); b2.y = __float2half(2.0f * v.w);
        *(__half2*)(covh + idx) = a;
        *(__half2*)(covh + idx + 2) = b;
        *(__half2*)(covh2 + idx) = a2;
        *(__half2*)(covh2 + idx + 2) = b2;
    }
}

__device__ __noinline__ void prep_lw_tile(const float* __restrict__ lw,
                                          __half* __restrict__ lwh, int l, int tid)
{
    const int base = l * 65536;
    for (int j = 0; j < 256; j++) {
        const int idx = base + j * 256 + tid;
        const int n = idx >> 11;
        lwh[idx] = (n < OUT_F) ? __float2half(lw[idx]) : __float2half(0.0f);
    }
}

// ---------------- fused persistent kernel: prep + 3 GEMM phases ----------------
__global__ void __launch_bounds__(NTH, 2)
gp_fused(const float* __restrict__ Din, const float* __restrict__ Win,
         const float* __restrict__ covin, const float* __restrict__ lwin,
         const __half* __restrict__ Abh, const __half* __restrict__ Bbh,
         const __half* __restrict__ Phih, const __half* __restrict__ covh,
         const __half* __restrict__ covh2, const __half* __restrict__ lwh,
         __half* __restrict__ AbhW, __half* __restrict__ BbhW,
         __half* __restrict__ covhW, __half* __restrict__ covh2W, __half* __restrict__ lwhW,
         __half* __restrict__ PhihW, float* __restrict__ diagp,
         const float* __restrict__ biasb, const float* __restrict__ lb,
         float* __restrict__ outp, int* __restrict__ sync)
{
    extern __shared__ float dyn[];
    __shared__ int s_tile;
    const int tid = threadIdx.x;
    const int wid = tid >> 5, lane = tid & 31;
    const int g = lane >> 2, t = lane & 3;
    const int warpM = wid >> 2, warpN = wid & 3;   // 2x4 warp grid, 64x32 warp tiles
    const uint32_t sbase = smem_u32(dyn);

    const uint32_t aOff = (uint32_t)((((warpM * 64 + ((lane >> 3) & 1) * 8 + (lane & 7)) * LDSH)
                                      + ((lane >> 4) & 1) * 8) * 2);
    const uint32_t bOff = (uint32_t)(AB_BYTES
                                      + (((warpN * 32 + ((lane >> 4) & 1) * 8 + (lane & 7)) * LDSH
                                      + ((lane >> 3) & 1) * 8) * 2));

    for (;;) {
        if (tid == 0) s_tile = atomicAdd(sync + S_CTR, 1);
        __syncthreads();
        const int tile = s_tile;
        if (tile >= T_END) break;

        // -------- prep phases --------
        if (tile < TP_G1) {
            if (tile < TP_D) {
                prep_w_tile(Win, BbhW, dyn, tile, tid);
                __threadfence(); __syncthreads();
                if (tid == 0) atomicAdd(sync + S_W, 1);
            } else if (tile < TP_COV) {
                const int d = tile - TP_D;
                prep_d_tile(Din, AbhW, d, tid);
                __threadfence(); __syncthreads();
                if (tid == 0) atomicAdd(sync + S_D + (d >> 1), 1);
            } else if (tile < TP_LW) {
                prep_cov_tile(covin, covhW, covh2W, tile - TP_COV, tid);
                __threadfence(); __syncthreads();
                if (tid == 0) atomicAdd(sync + S_COV, 1);
            } else {
                prep_lw_tile(lwin, lwhW, tile - TP_LW, tid);
                __threadfence(); __syncthreads();
                if (tid == 0) atomicAdd(sync + S_LW, 1);
            }
            continue;
        }

        // -------- GEMM phases --------
        int mode, rowb, cblk;
        if (tile < TP_G2)      { mode = 0; rowb = (tile - TP_G1) >> 4; cblk = (tile - TP_G1) & 15; }
        else if (tile < TP_G3) { mode = 1; rowb = (tile - TP_G2) >> 4; cblk = (tile - TP_G2) & 15; }
        else                   { mode = 2; rowb = (tile - TP_G3) >> 3; cblk = (tile - TP_G3) & 7; }
        const int rowTile = rowb * BM, colTile = cblk * BN;

        const __half *Aptr, *Bptr;
        int K, nIter;
        if (mode == 0)      { Aptr = Abh;  Bptr = Bbh;  K = KBIG; nIter = KBIG / BKB; }
        else if (mode == 1) { Aptr = Phih; Bptr = covh; K = RFF;  nIter = (colTile + BN) / BKB; }
        else                { Aptr = Phih; Bptr = lwh;  K = RFF;  nIter = RFF / BKB; }

        // dependency spin
        if (tid == 0) {
            if (mode == 0) {
                while (atomicAdd(sync + S_W, 0) < 32 ||
                       atomicAdd(sync + S_D + rowb, 0) < 2) __nanosleep(64);
            } else if (mode == 1) {
                while (atomicAdd(sync + S_COV, 0) < 64 ||
                       atomicAdd(sync + S_G1 + rowb, 0) < 16) __nanosleep(64);
            } else {
                while (atomicAdd(sync + S_LW, 0) < 32 ||
                       atomicAdd(sync + S_G2 + rowb, 0) < 16) __nanosleep(64);
            }
            __threadfence();
        }
        __syncthreads();

        float acc[4][4][4];
        #pragma unroll
        for (int mt = 0; mt < 4; mt++)
            #pragma unroll
            for (int nt = 0; nt < 4; nt++)
                #pragma unroll
                for (int r = 0; r < 4; r++) acc[mt][nt][r] = 0.0f;

        #define ISSUEH(it, s) do {                                                 \
            const int _k0 = (it) * BKB;                                            \
            const __half* _bs = (mode == 1 && _k0 < colTile) ? covh2 : Bptr;       \
            _Pragma("unroll")                                                      \
            for (int j = 0; j < 4; j++) {                                          \
                int f = tid + NTH * j;                                             \
                int r = f >> 3, q = f & 7;                                         \
                uint32_t d = sbase + (uint32_t)(s) * STAGE_BYTES_B + (uint32_t)((r * LDSH + q * 8) * 2); \
                cp16(d, Aptr + (size_t)(rowTile + r) * K + _k0 + q * 8);           \
            }                                                                      \
            _Pragma("unroll")                                                      \
            for (int j = 0; j < 4; j++) {                                          \
                int f = tid + NTH * j;                                             \
                int r = f >> 3, q = f & 7;                                         \
                uint32_t d = sbase + (uint32_t)(s) * STAGE_BYTES_B + (uint32_t)(AB_BYTES + (r * LDSH + q * 8) * 2); \
                cp16(d, _bs + (size_t)(colTile + r) * K + _k0 + q * 8);            \
            }                                                                      \
            cp_commit();                                                           \
        } while (0)

        ISSUEH(0, 0);
        ISSUEH(1, 1);

        int s = 0;
        for (int it = 0; it < nIter; ++it) {
            if (it + 1 < nIter) cp_wait<1>(); else cp_wait<0>();
            __syncthreads();
            if (it + 2 < nIter) ISSUEH(it + 2, (s + 2) % NSTAGE);

            const uint32_t aB = sbase + (uint32_t)s * STAGE_BYTES_B + aOff;
            const uint32_t bB = sbase + (uint32_t)s * STAGE_BYTES_B + bOff;
            #pragma unroll
            for (int kk = 0; kk < 4; kk++) {
                uint32_t af[4][4], bf[4][2];
                #pragma unroll
                for (int mt = 0; mt < 4; mt++)
                    ldsm_x4(af[mt], aB + (uint32_t)((mt * 16 * LDSH + kk * 16) * 2));
                #pragma unroll
                for (int np = 0; np < 2; np++) {
                    uint32_t r4[4];
                    ldsm_x4(r4, bB + (uint32_t)((np * 16 * LDSH + kk * 16) * 2));
                    bf[2 * np][0] = r4[0]; bf[2 * np][1] = r4[1];
                    bf[2 * np + 1][0] = r4[2]; bf[2 * np + 1][1] = r4[3];
                }
                #pragma unroll
                for (int mt = 0; mt < 4; mt++)
                    #pragma unroll
                    for (int nt = 0; nt < 4; nt++)
                        mma_f16(acc[mt][nt], af[mt], bf[nt]);
            }
            s = (s + 1 == NSTAGE) ? 0 : s + 1;
        }
        __syncthreads();

        // ---------------- epilogues ----------------
        if (mode == 0) {
            #pragma unroll
            for (int mt = 0; mt < 4; mt++)
                #pragma unroll
                for (int h = 0; h < 2; h++) {
                    const int R = rowTile + warpM * 64 + mt * 16 + g + h * 8;
                    __half* oph = PhihW + (size_t)R * RFF;
                    #pragma unroll
                    for (int nt = 0; nt < 4; nt++) {
                        const int C = colTile + warpN * 32 + nt * 8 + 2 * t;
                        float2 bb = *(const float2*)(biasb + C);
                        __half2 hh;
                        hh.x = __float2half(cosf(acc[mt][nt][h * 2 + 0] + bb.x) * INV_RFF_SCALAR);
                        hh.y = __float2half(cosf(acc[mt][nt][h * 2 + 1] + bb.y) * INV_RFF_SCALAR);
                        *(__half2*)(oph + C) = hh;
                    }
                }
            __threadfence();
            __syncthreads();
            if (tid == 0) atomicAdd(sync + S_G1 + rowb, 1);
        } else if (mode == 1) {
            float* red = dyn;  // [128][4]
            #pragma unroll
            for (int mt = 0; mt < 4; mt++)
                #pragma unroll
                for (int h = 0; h < 2; h++) {
                    const int lr = warpM * 64 + mt * 16 + g + h * 8;
                    const __half* pr = Phih + (size_t)(rowTile + lr) * RFF;
                    float sum = 0.0f;
                    #pragma unroll
                    for (int nt = 0; nt < 4; nt++) {
                        const int C = colTile + warpN * 32 + nt * 8 + 2 * t;
                        __half2 p = __ldcg((const __half2*)(pr + C));
                        sum = fmaf(acc[mt][nt][h * 2 + 0], __half2float(p.x), sum);
                        sum = fmaf(acc[mt][nt][h * 2 + 1], __half2float(p.y), sum);
                    }
                    sum += __shfl_xor_sync(0xffffffffu, sum, 1);
                    sum += __shfl_xor_sync(0xffffffffu, sum, 2);
                    if (t == 0) red[lr * 4 + warpN] = sum;
                }
            __syncthreads();
            if (tid < 128) {
                float sum = red[tid * 4 + 0] + red[tid * 4 + 1] + red[tid * 4 + 2] + red[tid * 4 + 3];
                diagp[(size_t)cblk * NROWS + rowTile + tid] = sum;
            }
            __threadfence();
            __syncthreads();
            if (tid == 0) atomicAdd(sync + S_G2 + rowb, 1);
        } else {
            float* scale = dyn;  // [128]
            if (tid < 128) {
                float dg = 0.0f;
                #pragma unroll
                for (int p = 0; p < 16; p++) dg += __ldcg(diagp + (size_t)p * NROWS + rowTile + tid);
                scale[tid] = rsqrtf(1.0f + MFF * dg);
            }
            __syncthreads();
            #pragma unroll
            for (int mt = 0; mt < 4; mt++)
                #pragma unroll
                for (int h = 0; h < 2; h++) {
                    const int lr = warpM * 64 + mt * 16 + g + h * 8;
                    const int R = rowTile + lr;
                    const float sc = scale[lr];
                    float* op = outp + (size_t)R * OUT_F;
                    #pragma unroll
                    for (int nt = 0; nt < 4; nt++) {
                        const int C = colTile + warpN * 32 + nt * 8 + 2 * t;
                        if (C < OUT_F) {
                            float2 bb = *(const float2*)(lb + C);
                            float2 o;
                            o.x = (acc[mt][nt][h * 2 + 0] + bb.x) * sc;
                            o.y = (acc[mt][nt][h * 2 + 1] + bb.y) * sc;
                            *(float2*)(op + C) = o;
                        }
                    }
                }
            __syncthreads();
        }
        #undef ISSUEH
    }
}

// ---------------- host ----------------
extern "C" void kernel_launch(void* const* d_in, const int* in_sizes, int n_in,
                              void* d_out, int out_size)
{
    const float* D   = (const float*)d_in[0];
    const float* W   = (const float*)d_in[1];
    const float* b   = (const float*)d_in[2];
    const float* lw  = (const float*)d_in[3];
    const float* lb  = (const float*)d_in[4];
    const float* cov = (const float*)d_in[5];
    float* out = (float*)d_out;

    float *diagp;
    __half *Phih, *covh, *covh2, *lwh, *Abh, *Bbh;
    int* sync;
    cudaGetSymbolAddress((void**)&Phih,  g_Phih);
    cudaGetSymbolAddress((void**)&covh,  g_covh);
    cudaGetSymbolAddress((void**)&covh2, g_covh2);
    cudaGetSymbolAddress((void**)&lwh,   g_lwh);
    cudaGetSymbolAddress((void**)&Abh,   g_Abh);
    cudaGetSymbolAddress((void**)&Bbh,   g_Bbh);
    cudaGetSymbolAddress((void**)&diagp, g_diag_part);
    cudaGetSymbolAddress((void**)&sync,  g_sync);

    const int smem = NSTAGE * STAGE_BYTES_B;  // 110592 bytes
    cudaFuncSetAttribute(gp_fused, cudaFuncAttributeMaxDynamicSharedMemorySize, smem);

    cudaMemsetAsync(sync, 0, S_TOT * sizeof(int));

    gp_fused<<<GRID_P, NTH, smem>>>(
        D, W, cov, lw,
        Abh, Bbh, Phih, covh, covh2, lwh,
        Abh, Bbh, covh, covh2, lwh,
        Phih, diagp, b, lb, out, sync);
}

// round 17
// speedup vs baseline: 1.1348x; 1.1348x over previous
#include <cuda_runtime.h>
#include <cuda_fp16.h>
#include <math.h>
#include <stdint.h>

// ---------------- problem constants ----------------
#define NROWS 8192
#define IN_F  512
#define RFF   2048
#define OUT_F 1000
#define OUT_P 1024
#define KBIG  (3*IN_F)                 // 1536: [Dhi|Dlo|Dhi] x [Whi|Whi|Wlo] (fp16)
#define INV_RFF_SCALAR (1.0f/32.0f)
#define MFF   25.0f

// ---------------- fp16 tiling ----------------
#define BM 128
#define BN 128
#define BKB 64
#define LDSH 72                        // halves per smem row (144 B)
#define AB_BYTES (128*LDSH*2)          // 18432
#define STAGE_BYTES_B (2*AB_BYTES)     // 36864
#define NSTAGE 3
#define NTH 256                        // 8 warps, 2x4 grid, 64x32 warp tiles
#define GRID_P 296

// queue: slots [0,1280): even -> G1 tile q/2 (640), odd -> prep tile (512 cov + 128 lw)
//        [1280,1664): G1 tiles 640..1023
//        [1664,2688): G2 tiles
//        [2688,3200): G3 tiles
#define Q_ALT  1280
#define Q_G1E  1664
#define Q_G2E  2688
#define T_END  3200
#define N_COV  512

// sync layout
#define S_CTR 0
#define S_COV 1
#define S_LW  2
#define S_G1  3     // 64 entries
#define S_G2  67    // 64 entries
#define S_TOT 131

// ---------------- device scratch ----------------
__device__ __half g_Phih [NROWS*RFF];
__device__ __half g_covh [RFF*RFF];
__device__ __half g_covh2[RFF*RFF];
__device__ __half g_lwh  [OUT_P*RFF];
__device__ __half g_Abh[NROWS*KBIG];
__device__ __half g_Bbh[RFF*KBIG];
__device__ float  g_diag_part[16*NROWS];
__device__ int    g_sync[S_TOT];

// ---------------- helpers ----------------
__device__ __forceinline__ uint32_t smem_u32(const void* p) {
    uint32_t r;
    asm("{ .reg .u64 t; cvta.to.shared.u64 t, %1; cvt.u32.u64 %0, t; }" : "=r"(r) : "l"(p));
    return r;
}
__device__ __forceinline__ void cp16(uint32_t d, const void* s) {
    asm volatile("cp.async.cg.shared.global [%0], [%1], 16;" :: "r"(d), "l"(s));
}
__device__ __forceinline__ void cp_commit() { asm volatile("cp.async.commit_group;"); }
template <int N> __device__ __forceinline__ void cp_wait() {
    asm volatile("cp.async.wait_group %0;" :: "n"(N));
}
__device__ __forceinline__ void ldsm_x4(uint32_t* r, uint32_t a) {
    asm volatile("ldmatrix.sync.aligned.m8n8.x4.shared.b16 {%0,%1,%2,%3}, [%4];"
        : "=r"(r[0]), "=r"(r[1]), "=r"(r[2]), "=r"(r[3]) : "r"(a));
}
__device__ __forceinline__ void mma_f16(float* c, const uint32_t* a, const uint32_t* b) {
    asm volatile(
        "mma.sync.aligned.m16n8k16.row.col.f32.f16.f16.f32 "
        "{%0,%1,%2,%3}, {%4,%5,%6,%7}, {%8,%9}, {%0,%1,%2,%3};"
        : "+f"(c[0]), "+f"(c[1]), "+f"(c[2]), "+f"(c[3])
        : "r"(a[0]), "r"(a[1]), "r"(a[2]), "r"(a[3]), "r"(b[0]), "r"(b[1]));
}

// ---------------- standalone prep kernel (D split + W split only) ----------------
#define PD_BLKS 16384
#define PW_BLKS 1024
__global__ void prep_dw(const float* __restrict__ D, const float* __restrict__ W,
                        __half* __restrict__ Abh, __half* __restrict__ Bbh)
{
    const int blk = blockIdx.x;
    const int tid = threadIdx.x;
    if (blk < PD_BLKS) {
        int idx = blk * 256 + tid;
        int r = idx >> 9, k = idx & (IN_F - 1);
        float x = D[idx];
        __half hi = __float2half(x);
        __half lo = __float2half(x - __half2float(hi));
        __half* p = Abh + (size_t)r * KBIG;
        p[k] = hi; p[IN_F + k] = lo; p[2 * IN_F + k] = hi;
    } else {
        __shared__ float t[32][33];
        int wb = blk - PD_BLKS;
        int nb = (wb & 63) * 32, kb = (wb >> 6) * 32;
        int tx = tid & 31, ty0 = tid >> 5;
        #pragma unroll
        for (int i = 0; i < 32; i += 8) {
            int ty = ty0 + i;
            t[ty][tx] = W[(size_t)(kb + ty) * RFF + nb + tx];
        }
        __syncthreads();
        #pragma unroll
        for (int i = 0; i < 32; i += 8) {
            int ty = ty0 + i;
            int n = nb + ty, k = kb + tx;
            float x = t[tx][ty];
            __half hi = __float2half(x);
            __half lo = __float2half(x - __half2float(hi));
            __half* p = Bbh + (size_t)n * KBIG;
            p[k] = hi; p[IN_F + k] = hi; p[2 * IN_F + k] = lo;
        }
    }
}

// ---------------- fine-grained in-queue prep workers (noinline: reg budget) ----------------
__device__ __noinline__ void prep_cov_tile(const float* __restrict__ cov,
                                           __half* __restrict__ covh,
                                           __half* __restrict__ covh2, int c, int tid)
{
    const int base = c * 8192;   // 4 rows x 2048 floats
    #pragma unroll
    for (int j = 0; j < 8; j++) {
        const int idx = base + (j * 256 + tid) * 4;
        float4 v = *(const float4*)(cov + idx);
        __half2 a, b, a2, b2;
        a.x  = __float2half(v.x);        a.y  = __float2half(v.y);
        b.x  = __float2half(v.z);        b.y  = __float2half(v.w);
        a2.x = __float2half(2.0f * v.x); a2.y = __float2half(2.0f * v.y);
        b2.x = __float2half(2.0f * v.z); b2.y = __float2half(2.0f * v.w);
        *(__half2*)(covh + idx) = a;
        *(__half2*)(covh + idx + 2) = b;
        *(__half2*)(covh2 + idx) = a2;
        *(__half2*)(covh2 + idx + 2) = b2;
    }
}

__device__ __noinline__ void prep_lw_tile(const float* __restrict__ lw,
                                          __half* __restrict__ lwh, int l, int tid)
{
    const int base = l * 16384;  // 8 rows x 2048
    #pragma unroll
    for (int j = 0; j < 16; j++) {
        const int idx = base + (j * 256 + tid) * 4;
        const int n = idx >> 11;
        float4 v = (n < OUT_F) ? *(const float4*)(lw + idx) : make_float4(0.f, 0.f, 0.f, 0.f);
        __half2 a, b;
        a.x = __float2half(v.x); a.y = __float2half(v.y);
        b.x = __float2half(v.z); b.y = __float2half(v.w);
        *(__half2*)(lwh + idx) = a;
        *(__half2*)(lwh + idx + 2) = b;
    }
}

// ---------------- fused persistent fp16 GEMM + interleaved cov/lw prep ----------------
__global__ void __launch_bounds__(NTH, 2)
gp_fused(const float* __restrict__ covin, const float* __restrict__ lwin,
         const __half* __restrict__ Abh, const __half* __restrict__ Bbh,
         const __half* __restrict__ Phih, const __half* __restrict__ covh,
         const __half* __restrict__ covh2, const __half* __restrict__ lwh,
         __half* __restrict__ covhW, __half* __restrict__ covh2W, __half* __restrict__ lwhW,
         __half* __restrict__ PhihW, float* __restrict__ diagp,
         const float* __restrict__ biasb, const float* __restrict__ lb,
         float* __restrict__ outp, int* __restrict__ sync)
{
    extern __shared__ float dyn[];
    __shared__ int s_tile;
    const int tid = threadIdx.x;
    const int wid = tid >> 5, lane = tid & 31;
    const int g = lane >> 2, t = lane & 3;
    const int warpM = wid >> 2, warpN = wid & 3;   // 2x4 warp grid, 64x32 warp tiles
    const uint32_t sbase = smem_u32(dyn);

    const uint32_t aOff = (uint32_t)((((warpM * 64 + ((lane >> 3) & 1) * 8 + (lane & 7)) * LDSH)
                                      + ((lane >> 4) & 1) * 8) * 2);
    const uint32_t bOff = (uint32_t)(AB_BYTES
                                      + (((warpN * 32 + ((lane >> 4) & 1) * 8 + (lane & 7)) * LDSH
                                      + ((lane >> 3) & 1) * 8) * 2));

    for (;;) {
        if (tid == 0) s_tile = atomicAdd(sync + S_CTR, 1);
        __syncthreads();
        const int tile = s_tile;
        if (tile >= T_END) break;

        // -------- interleaved prep tiles (odd slots of alternating region) --------
        if (tile < Q_ALT && (tile & 1)) {
            const int p = tile >> 1;
            if (p < N_COV) {
                prep_cov_tile(covin, covhW, covh2W, p, tid);
                __threadfence(); __syncthreads();
                if (tid == 0) atomicAdd(sync + S_COV, 1);
            } else {
                prep_lw_tile(lwin, lwhW, p - N_COV, tid);
                __threadfence(); __syncthreads();
                if (tid == 0) atomicAdd(sync + S_LW, 1);
            }
            continue;
        }

        // -------- GEMM phases --------
        int mode, rowb, cblk;
        if (tile < Q_ALT)      { const int q = tile >> 1;          mode = 0; rowb = q >> 4; cblk = q & 15; }
        else if (tile < Q_G1E) { const int q = 640 + tile - Q_ALT; mode = 0; rowb = q >> 4; cblk = q & 15; }
        else if (tile < Q_G2E) { const int q = tile - Q_G1E;       mode = 1; rowb = q >> 4; cblk = q & 15; }
        else                   { const int q = tile - Q_G2E;       mode = 2; rowb = q >> 3; cblk = q & 7; }
        const int rowTile = rowb * BM, colTile = cblk * BN;

        const __half *Aptr, *Bptr;
        int K, nIter;
        if (mode == 0)      { Aptr = Abh;  Bptr = Bbh;  K = KBIG; nIter = KBIG / BKB; }
        else if (mode == 1) { Aptr = Phih; Bptr = covh; K = RFF;  nIter = (colTile + BN) / BKB; }
        else                { Aptr = Phih; Bptr = lwh;  K = RFF;  nIter = RFF / BKB; }

        // dependency spin (release/acquire via threadfence + atomics)
        if (mode != 0) {
            if (tid == 0) {
                if (mode == 1) {
                    while (atomicAdd(sync + S_COV, 0) < N_COV ||
                           atomicAdd(sync + S_G1 + rowb, 0) < 16) __nanosleep(64);
                } else {
                    while (atomicAdd(sync + S_LW, 0) < 128 ||
                           atomicAdd(sync + S_G2 + rowb, 0) < 16) __nanosleep(64);
                }
                __threadfence();
            }
            __syncthreads();
        }

        float acc[4][4][4];
        #pragma unroll
        for (int mt = 0; mt < 4; mt++)
            #pragma unroll
            for (int nt = 0; nt < 4; nt++)
                #pragma unroll
                for (int r = 0; r < 4; r++) acc[mt][nt][r] = 0.0f;

        #define ISSUEH(it, s) do {                                                 \
            const int _k0 = (it) * BKB;                                            \
            const __half* _bs = (mode == 1 && _k0 < colTile) ? covh2 : Bptr;       \
            _Pragma("unroll")                                                      \
            for (int j = 0; j < 4; j++) {                                          \
                int f = tid + NTH * j;                                             \
                int r = f >> 3, q = f & 7;                                         \
                uint32_t d = sbase + (uint32_t)(s) * STAGE_BYTES_B + (uint32_t)((r * LDSH + q * 8) * 2); \
                cp16(d, Aptr + (size_t)(rowTile + r) * K + _k0 + q * 8);           \
            }                                                                      \
            _Pragma("unroll")                                                      \
            for (int j = 0; j < 4; j++) {                                          \
                int f = tid + NTH * j;                                             \
                int r = f >> 3, q = f & 7;                                         \
                uint32_t d = sbase + (uint32_t)(s) * STAGE_BYTES_B + (uint32_t)(AB_BYTES + (r * LDSH + q * 8) * 2); \
                cp16(d, _bs + (size_t)(colTile + r) * K + _k0 + q * 8);            \
            }                                                                      \
            cp_commit();                                                           \
        } while (0)

        ISSUEH(0, 0);
        ISSUEH(1, 1);

        int s = 0;
        for (int it = 0; it < nIter; ++it) {
            if (it + 1 < nIter) cp_wait<1>(); else cp_wait<0>();
            __syncthreads();
            if (it + 2 < nIter) ISSUEH(it + 2, (s + 2) % NSTAGE);

            const uint32_t aB = sbase + (uint32_t)s * STAGE_BYTES_B + aOff;
            const uint32_t bB = sbase + (uint32_t)s * STAGE_BYTES_B + bOff;
            #pragma unroll
            for (int kk = 0; kk < 4; kk++) {
                uint32_t af[4][4], bf[4][2];
                #pragma unroll
                for (int mt = 0; mt < 4; mt++)
                    ldsm_x4(af[mt], aB + (uint32_t)((mt * 16 * LDSH + kk * 16) * 2));
                #pragma unroll
                for (int np = 0; np < 2; np++) {
                    uint32_t r4[4];
                    ldsm_x4(r4, bB + (uint32_t)((np * 16 * LDSH + kk * 16) * 2));
                    bf[2 * np][0] = r4[0]; bf[2 * np][1] = r4[1];
                    bf[2 * np + 1][0] = r4[2]; bf[2 * np + 1][1] = r4[3];
                }
                #pragma unroll
                for (int mt = 0; mt < 4; mt++)
                    #pragma unroll
                    for (int nt = 0; nt < 4; nt++)
                        mma_f16(acc[mt][nt], af[mt], bf[nt]);
            }
            s = (s + 1 == NSTAGE) ? 0 : s + 1;
        }
        __syncthreads();

        // ---------------- epilogues ----------------
        if (mode == 0) {
            #pragma unroll
            for (int mt = 0; mt < 4; mt++)
                #pragma unroll
                for (int h = 0; h < 2; h++) {
                    const int R = rowTile + warpM * 64 + mt * 16 + g + h * 8;
                    __half* oph = PhihW + (size_t)R * RFF;
                    #pragma unroll
                    for (int nt = 0; nt < 4; nt++) {
                        const int C = colTile + warpN * 32 + nt * 8 + 2 * t;
                        float2 bb = *(const float2*)(biasb + C);
                        __half2 hh;
                        hh.x = __float2half(cosf(acc[mt][nt][h * 2 + 0] + bb.x) * INV_RFF_SCALAR);
                        hh.y = __float2half(cosf(acc[mt][nt][h * 2 + 1] + bb.y) * INV_RFF_SCALAR);
                        *(__half2*)(oph + C) = hh;
                    }
                }
            __threadfence();
            __syncthreads();
            if (tid == 0) atomicAdd(sync + S_G1 + rowb, 1);
        } else if (mode == 1) {
            float* red = dyn;  // [128][4]
            #pragma unroll
            for (int mt = 0; mt < 4; mt++)
                #pragma unroll
                for (int h = 0; h < 2; h++) {
                    const int lr = warpM * 64 + mt * 16 + g + h * 8;
                    const __half* pr = Phih + (size_t)(rowTile + lr) * RFF;
                    float sum = 0.0f;
                    #pragma unroll
                    for (int nt = 0; nt < 4; nt++) {
                        const int C = colTile + warpN * 32 + nt * 8 + 2 * t;
                        __half2 p = __ldcg((const __half2*)(pr + C));
                        sum = fmaf(acc[mt][nt][h * 2 + 0], __half2float(p.x), sum);
                        sum = fmaf(acc[mt][nt][h * 2 + 1], __half2float(p.y), sum);
                    }
                    sum += __shfl_xor_sync(0xffffffffu, sum, 1);
                    sum += __shfl_xor_sync(0xffffffffu, sum, 2);
                    if (t == 0) red[lr * 4 + warpN] = sum;
                }
            __syncthreads();
            if (tid < 128) {
                float sum = red[tid * 4 + 0] + red[tid * 4 + 1] + red[tid * 4 + 2] + red[tid * 4 + 3];
                diagp[(size_t)cblk * NROWS + rowTile + tid] = sum;
            }
            __threadfence();
            __syncthreads();
            if (tid == 0) atomicAdd(sync + S_G2 + rowb, 1);
        } else {
            float* scale = dyn;  // [128]
            if (tid < 128) {
                float dg = 0.0f;
                #pragma unroll
                for (int p = 0; p < 16; p++) dg += __ldcg(diagp + (size_t)p * NROWS + rowTile + tid);
                scale[tid] = rsqrtf(1.0f + MFF * dg);
            }
            __syncthreads();
            #pragma unroll
            for (int mt = 0; mt < 4; mt++)
                #pragma unroll
                for (int h = 0; h < 2; h++) {
                    const int lr = warpM * 64 + mt * 16 + g + h * 8;
                    const int R = rowTile + lr;
                    const float sc = scale[lr];
                    float* op = outp + (size_t)R * OUT_F;
                    #pragma unroll
                    for (int nt = 0; nt < 4; nt++) {
                        const int C = colTile + warpN * 32 + nt * 8 + 2 * t;
                        if (C < OUT_F) {
                            float2 bb = *(const float2*)(lb + C);
                            float2 o;
                            o.x = (acc[mt][nt][h * 2 + 0] + bb.x) * sc;
                            o.y = (acc[mt][nt][h * 2 + 1] + bb.y) * sc;
                            *(float2*)(op + C) = o;
                        }
                    }
                }
            __syncthreads();
        }
        #undef ISSUEH
    }
}

// ---------------- host ----------------
extern "C" void kernel_launch(void* const* d_in, const int* in_sizes, int n_in,
                              void* d_out, int out_size)
{
    const float* D   = (const float*)d_in[0];
    const float* W   = (const float*)d_in[1];
    const float* b   = (const float*)d_in[2];
    const float* lw  = (const float*)d_in[3];
    const float* lb  = (const float*)d_in[4];
    const float* cov = (const float*)d_in[5];
    float* out = (float*)d_out;

    float *diagp;
    __half *Phih, *covh, *covh2, *lwh, *Abh, *Bbh;
    int* sync;
    cudaGetSymbolAddress((void**)&Phih,  g_Phih);
    cudaGetSymbolAddress((void**)&covh,  g_covh);
    cudaGetSymbolAddress((void**)&covh2, g_covh2);
    cudaGetSymbolAddress((void**)&lwh,   g_lwh);
    cudaGetSymbolAddress((void**)&Abh,   g_Abh);
    cudaGetSymbolAddress((void**)&Bbh,   g_Bbh);
    cudaGetSymbolAddress((void**)&diagp, g_diag_part);
    cudaGetSymbolAddress((void**)&sync,  g_sync);

    const int smem = NSTAGE * STAGE_BYTES_B;  // 110592 bytes
    cudaFuncSetAttribute(gp_fused, cudaFuncAttributeMaxDynamicSharedMemorySize, smem);

    cudaMemsetAsync(sync, 0, S_TOT * sizeof(int));

    prep_dw<<<PD_BLKS + PW_BLKS, 256>>>(D, W, Abh, Bbh);

    gp_fused<<<GRID_P, NTH, smem>>>(
        cov, lw,
        Abh, Bbh, Phih, covh, covh2, lwh,
        covh, covh2, lwh,
        Phih, diagp, b, lb, out, sync);
}